// round 15
// baseline (speedup 1.0000x reference)
#include <cuda_runtime.h>
#include <stdint.h>

// SparseGather: out[m, i, j, c] = inputs[n_m, y0_m + i, x0_m + j, c]
// inputs: (N=4, H=512, W=512, C=64) fp32
// active_block_indices: (M=4096, 3) int32 -> (n, by, bx); y0 = by*16, x0 = bx*16
// out: (M, 16, 16, 64) fp32
//
// FINAL — converged optimum of the 14-round study.
//   * Traffic at mandatory floor: 268 MB output writes + ~175 MB unique-block
//     reads (blocks are 16-aligned -> no partial overlap; exact duplicates
//     fully L2-deduped, matching binomial-unique expectation to ~3%).
//   * Ceiling is mechanism-independent: LSU-128b, LSU-256b, cg/cs/evict_last
//     policies, persistent grid, and TMA cp.async.bulk all plateau at
//     6.0-6.15 TB/s => mixed ~60/40 W/R DRAM stream (bus turnaround) is the
//     limiter. Occupancy, issue, and LTS are non-binding.
//   * Granularity sweep (16/8/4/2 rows/CTA -> 75.3/76.1/76.9/75.2 DRAM%)
//     fixes 4 rows/CTA as the optimum.
//   Measured noise band: 72.6-73.7 us ncu, 78.1-78.7 us wall, rel_err 0.
//
// Units of float4 (C=64 -> 16 float4 per pixel):
//   C4   = 16
//   WC4  = 512 * 16 = 8192   (row stride, float4)
//   HWC4 = 512 * WC4         (image stride, float4)

#define C4   16
#define WC4  (512 * C4)
#define HWC4 (512 * WC4)

__global__ __launch_bounds__(256) void sparse_gather_kernel(
    const float4* __restrict__ in,
    const int*    __restrict__ idx,
    float4*       __restrict__ out)
{
    const int b  = blockIdx.x;     // 0 .. 4*M-1
    const int m  = b >> 2;         // block index
    const int r0 = (b & 3) << 2;   // row offset: 0, 4, 8, 12
    const int t  = threadIdx.x;    // 0..255

    const int n  = idx[3 * m + 0];
    const int by = idx[3 * m + 1];
    const int bx = idx[3 * m + 2];

    const float4* src = in
        + (size_t)n * HWC4
        + (size_t)(by * 16 + r0) * WC4
        + (size_t)(bx * 16) * C4;

    float4* dst = out + (size_t)m * 4096 + (size_t)r0 * 256;

    // 4 rows; each row = 256 contiguous float4 on both sides.
    float4 v[4];
    #pragma unroll
    for (int r = 0; r < 4; ++r) {
        v[r] = __ldcg(&src[(size_t)r * WC4 + t]);   // L2-only read (no L1 alloc)
    }
    #pragma unroll
    for (int r = 0; r < 4; ++r) {
        __stcs(&dst[r * 256 + t], v[r]);            // evict-first streaming store
    }
}

extern "C" void kernel_launch(void* const* d_in, const int* in_sizes, int n_in,
                              void* d_out, int out_size)
{
    const float4* in  = (const float4*)d_in[0];
    const int*    idx = (const int*)d_in[2];   // active_block_indices
    float4*       out = (float4*)d_out;

    const int M = in_sizes[2] / 3;             // 4096

    sparse_gather_kernel<<<4 * M, 256>>>(in, idx, out);
}

// round 16
// speedup vs baseline: 1.0077x; 1.0077x over previous
#include <cuda_runtime.h>
#include <stdint.h>

// SparseGather: out[m, i, j, c] = inputs[n_m, y0_m + i, x0_m + j, c]
// inputs: (N=4, H=512, W=512, C=64) fp32
// active_block_indices: (M=4096, 3) int32 -> (n, by, bx); y0 = by*16, x0 = bx*16
// out: (M, 16, 16, 64) fp32
//
// R16 terminal probe: same per-thread work as the converged optimum
// (4x __ldcg float4 + 4x __stcs float4), but CTA=512 threads covering 8 rows:
//   - index loads amortized over 2x the bytes
//   - 32 KB fully-contiguous store range per CTA (longer DRAM write bursts)
//   - grid = 2*M = 8192, 4 CTAs/SM at 512 thr -> occupancy unchanged
// Everything else is the 15-round converged configuration (traffic at the
// 443 MB floor; 6.0-6.15 TB/s mechanism-independent mixed-stream ceiling).
//
// Units of float4 (C=64 -> 16 float4 per pixel):
//   C4   = 16
//   WC4  = 512 * 16 = 8192   (row stride, float4)
//   HWC4 = 512 * WC4         (image stride, float4)

#define C4   16
#define WC4  (512 * C4)
#define HWC4 (512 * WC4)

__global__ __launch_bounds__(512) void sparse_gather_kernel(
    const float4* __restrict__ in,
    const int*    __restrict__ idx,
    float4*       __restrict__ out)
{
    const int b  = blockIdx.x;       // 0 .. 2*M-1
    const int m  = b >> 1;           // block index
    const int r0 = (b & 1) << 3;     // row offset: 0 or 8
    const int t  = threadIdx.x;      // 0..511

    const int rA = t >> 8;           // 0 or 1: this thread's row pair base
    const int c  = t & 255;          // float4 index within row

    const int n  = idx[3 * m + 0];
    const int by = idx[3 * m + 1];
    const int bx = idx[3 * m + 2];

    const float4* src = in
        + (size_t)n * HWC4
        + (size_t)(by * 16 + r0) * WC4
        + (size_t)(bx * 16) * C4;

    float4* dst = out + (size_t)m * 4096 + (size_t)r0 * 256;

    // 8 rows split over two half-CTAs: threads 0-255 do rows 0,2,4,6;
    // threads 256-511 do rows 1,3,5,7. 4 loads + 4 stores per thread,
    // identical per-thread SASS to the converged optimum.
    float4 v[4];
    #pragma unroll
    for (int r = 0; r < 4; ++r) {
        v[r] = __ldcg(&src[(size_t)(2 * r + rA) * WC4 + c]);   // L2-only read
    }
    #pragma unroll
    for (int r = 0; r < 4; ++r) {
        __stcs(&dst[(2 * r + rA) * 256 + c], v[r]);            // streaming store
    }
}

extern "C" void kernel_launch(void* const* d_in, const int* in_sizes, int n_in,
                              void* d_out, int out_size)
{
    const float4* in  = (const float4*)d_in[0];
    const int*    idx = (const int*)d_in[2];   // active_block_indices
    float4*       out = (float4*)d_out;

    const int M = in_sizes[2] / 3;             // 4096

    sparse_gather_kernel<<<2 * M, 512>>>(in, idx, out);
}

// round 17
// speedup vs baseline: 1.0127x; 1.0049x over previous
#include <cuda_runtime.h>
#include <stdint.h>

// SparseGather: out[m, i, j, c] = inputs[n_m, y0_m + i, x0_m + j, c]
// inputs: (N=4, H=512, W=512, C=64) fp32
// active_block_indices: (M=4096, 3) int32 -> (n, by, bx); y0 = by*16, x0 = bx*16
// out: (M, 16, 16, 64) fp32
//
// FINAL — converged optimum of the 16-round study (best ncu sample: 72.51us).
//   * Traffic at mandatory floor: 268 MB output writes + ~175 MB unique-block
//     reads (16-aligned blocks -> no partial overlap; exact duplicates fully
//     L2-deduped, matching binomial-unique expectation to ~3%).
//   * Ceiling is mechanism-independent: LSU-128b, LSU-256b, cg/cs/evict_last
//     policies, persistent grid, CTA shapes 32..512 thr, and TMA
//     cp.async.bulk all plateau at 6.0-6.15 TB/s => mixed ~60/40 W/R DRAM
//     stream (bus turnaround) is the limiter. Occupancy/issue/LTS non-binding.
//   * Per-thread optimum: 4x 128-bit __ldcg + 4x __stcs (granularity sweep).
//   Measured noise band: 72.5-73.7 us ncu, 78.1-79.2 us wall, rel_err 0.
//
// Units of float4 (C=64 -> 16 float4 per pixel):
//   C4   = 16
//   WC4  = 512 * 16 = 8192   (row stride, float4)
//   HWC4 = 512 * WC4         (image stride, float4)

#define C4   16
#define WC4  (512 * C4)
#define HWC4 (512 * WC4)

__global__ __launch_bounds__(512) void sparse_gather_kernel(
    const float4* __restrict__ in,
    const int*    __restrict__ idx,
    float4*       __restrict__ out)
{
    const int b  = blockIdx.x;       // 0 .. 2*M-1
    const int m  = b >> 1;           // block index
    const int r0 = (b & 1) << 3;     // row offset: 0 or 8
    const int t  = threadIdx.x;      // 0..511

    const int rA = t >> 8;           // 0 or 1: this thread's row-pair base
    const int c  = t & 255;          // float4 index within row

    const int n  = idx[3 * m + 0];
    const int by = idx[3 * m + 1];
    const int bx = idx[3 * m + 2];

    const float4* src = in
        + (size_t)n * HWC4
        + (size_t)(by * 16 + r0) * WC4
        + (size_t)(bx * 16) * C4;

    float4* dst = out + (size_t)m * 4096 + (size_t)r0 * 256;

    // 8 rows split over two half-CTAs: threads 0-255 do rows 0,2,4,6;
    // threads 256-511 do rows 1,3,5,7. 4 loads + 4 stores per thread.
    float4 v[4];
    #pragma unroll
    for (int r = 0; r < 4; ++r) {
        v[r] = __ldcg(&src[(size_t)(2 * r + rA) * WC4 + c]);   // L2-only read
    }
    #pragma unroll
    for (int r = 0; r < 4; ++r) {
        __stcs(&dst[(2 * r + rA) * 256 + c], v[r]);            // streaming store
    }
}

extern "C" void kernel_launch(void* const* d_in, const int* in_sizes, int n_in,
                              void* d_out, int out_size)
{
    const float4* in  = (const float4*)d_in[0];
    const int*    idx = (const int*)d_in[2];   // active_block_indices
    float4*       out = (float4*)d_out;

    const int M = in_sizes[2] / 3;             // 4096

    sparse_gather_kernel<<<2 * M, 512>>>(in, idx, out);
}